// round 1
// baseline (speedup 1.0000x reference)
#include <cuda_runtime.h>

// Conv2d: x (32,128,56,56) fp32, W (256,128,3,3) fp32, b (256,) fp32
// out (32,256,56,56) fp32. stride 1, pad 1.
//
// Implicit-GEMM direct conv, FFMA baseline:
//   block tile: 8x8 spatial pixels x 128 Cout, one image
//   thread tile: 4 pixels x 8 Cout (32 accumulators)
//   K loop: Cin in chunks of 8 (16 iterations), smem-staged x halo + W slice
// Smem padding chosen for conflict-free LDS (x row stride 11, W cout stride 73).

#define CIN        128
#define COUT       256
#define HW         56
#define COUT_TILE  128
#define CIN_CHUNK  8
#define THREADS    256

__global__ __launch_bounds__(THREADS)
void Conv2d_2723009266574_kernel(const float* __restrict__ x,
                                 const float* __restrict__ Wt,
                                 const float* __restrict__ bias,
                                 float* __restrict__ out) {
    // grid: (49 spatial tiles, 2 cout tiles, 32 images)
    const int st    = blockIdx.x;
    const int h0    = (st / 7) * 8;
    const int w0    = (st % 7) * 8;
    const int cout0 = blockIdx.y * COUT_TILE;
    const int b     = blockIdx.z;

    // x halo tile: 8 cin x 10 rows x 10 cols, row stride padded to 11
    __shared__ float sx[CIN_CHUNK][10][11];
    // W tile: 128 cout x (8 cin * 3 * 3 = 72), padded to 73
    __shared__ float sw[COUT_TILE][73];

    const int tid = threadIdx.x;
    const int cg  = tid >> 4;          // 0..15 : cout group (8 couts each)
    const int pg  = tid & 15;          // 0..15 : pixel group (4 pixels each)
    const int py  = pg >> 1;           // 0..7
    const int px0 = (pg & 1) * 4;      // 0 or 4

    float acc[4][8];
    #pragma unroll
    for (int i = 0; i < 4; i++)
        #pragma unroll
        for (int j = 0; j < 8; j++)
            acc[i][j] = 0.0f;

    const long xb = (long)b * CIN * HW * HW;

    for (int c0 = 0; c0 < CIN; c0 += CIN_CHUNK) {
        // ---- stage x halo: 8 x 10 x 10 = 800 floats ----
        for (int idx = tid; idx < CIN_CHUNK * 100; idx += THREADS) {
            int c   = idx / 100;
            int rem = idx - c * 100;
            int r   = rem / 10;
            int col = rem - r * 10;
            int hh  = h0 - 1 + r;
            int ww  = w0 - 1 + col;
            float v = 0.0f;
            if (hh >= 0 && hh < HW && ww >= 0 && ww < HW)
                v = x[xb + ((long)(c0 + c) * HW + hh) * HW + ww];
            sx[c][r][col] = v;
        }
        // ---- stage W slice: 128 cout x 72 floats ----
        for (int idx = tid; idx < COUT_TILE * 72; idx += THREADS) {
            int j = idx / 72;
            int r = idx - j * 72;
            sw[j][r] = Wt[(long)(cout0 + j) * (CIN * 9) + c0 * 9 + r];
        }
        __syncthreads();

        #pragma unroll 2
        for (int c = 0; c < CIN_CHUNK; c++) {
            #pragma unroll
            for (int kh = 0; kh < 3; kh++) {
                #pragma unroll
                for (int kw = 0; kw < 3; kw++) {
                    float xv[4];
                    #pragma unroll
                    for (int i = 0; i < 4; i++)
                        xv[i] = sx[c][py + kh][px0 + kw + i];
                    float wv[8];
                    const int wofs = c * 9 + kh * 3 + kw;
                    #pragma unroll
                    for (int j = 0; j < 8; j++)
                        wv[j] = sw[cg * 8 + j][wofs];
                    #pragma unroll
                    for (int i = 0; i < 4; i++)
                        #pragma unroll
                        for (int j = 0; j < 8; j++)
                            acc[i][j] = fmaf(xv[i], wv[j], acc[i][j]);
                }
            }
        }
        __syncthreads();
    }

    // ---- epilogue: bias + store ----
    #pragma unroll
    for (int j = 0; j < 8; j++) {
        const int co = cout0 + cg * 8 + j;
        const float bb = bias[co];
        const long obase = (((long)b * COUT + co) * HW + (h0 + py)) * HW + w0 + px0;
        #pragma unroll
        for (int i = 0; i < 4; i++)
            out[obase + i] = acc[i][j] + bb;
    }
}

extern "C" void kernel_launch(void* const* d_in, const int* in_sizes, int n_in,
                              void* d_out, int out_size) {
    const float* x  = (const float*)d_in[0];
    const float* Wt = (const float*)d_in[1];
    const float* bb = (const float*)d_in[2];
    float* out      = (float*)d_out;

    dim3 grid(49, COUT / COUT_TILE, 32);   // 49 x 2 x 32 = 3136 blocks
    Conv2d_2723009266574_kernel<<<grid, THREADS>>>(x, Wt, bb, out);
}

// round 3
// speedup vs baseline: 3.8367x; 3.8367x over previous
#include <cuda_runtime.h>
#include <cstdint>

// ============================================================
// Conv2d 3x3 s1 p1: x(32,128,56,56)*W(256,128,3,3)+b -> (32,256,56,56)
// Shifted-GEMM conv on mma.sync.m16n8k8.tf32 (base sm_103 target —
// tcgen05 is unavailable: harness PTX targets sm_103, not sm_103a).
//   out[q,n] = sum_{s,c} xpad[b][c][q+off_s] * W[n][c][s],  q in 58x58 domain
// CTA: 128 pixels x 128 couts, 8 warps (warp = 32x64), K=9*128 in 36
// rounds of 32 cin, double-buffered smem, cp.async for W (pre-arranged
// in mma fragment order), per-fragment STS.128 for A.
// ============================================================

#define HW        56
#define PW        58
#define CSTRIDE   3584
#define CIN       128
#define COUT      256
#define BATCH     32
#define NROUNDS   36
#define MTILES    26
#define SA_BYTES  16384
#define SB_BYTES  16384
#define BUF_BYTES (SA_BYTES + SB_BYTES)

__device__ float    g_xpad[BATCH * CIN * CSTRIDE];   // tf32-rounded, zero-padded
__device__ uint32_t g_wrf[9 * 2 * 4 * 4096];         // W in fragment order

// ---------------- prep ----------------
__global__ void pad_kernel(const float* __restrict__ x) {
    long idx = (long)blockIdx.x * blockDim.x + threadIdx.x;
    const long total = (long)BATCH * CIN * CSTRIDE;
    if (idx >= total) return;
    int pos = (int)(idx % CSTRIDE);
    long bc = idx / CSTRIDE;
    float v = 0.0f;
    if (pos < PW * PW) {
        int h = pos / PW, w = pos % PW;
        if (h >= 1 && h <= HW && w >= 1 && w <= HW)
            v = x[bc * (HW * HW) + (long)(h - 1) * HW + (w - 1)];
    }
    asm("cvt.rna.tf32.f32 %0, %0;" : "+f"(v));
    g_xpad[idx] = v;
}

// g_wrf layout: block = (s*2+nb)*4+chunk (4096 u32 each);
// within = nt*256 + kt*64 + lane*2 + reg
// value = tf32( W[n][cin][s] ), n = nb*128+nt*8+lane/4,
//         cin = chunk*32+kt*8+(lane&3)+reg*4
__global__ void wrf_kernel(const float* __restrict__ W) {
    int idx = blockIdx.x * blockDim.x + threadIdx.x;
    if (idx >= 9 * 2 * 4 * 4096) return;
    int blk = idx >> 12, within = idx & 4095;
    int s = blk >> 3, nb = (blk >> 2) & 1, chunk = blk & 3;
    int nt = within >> 8, kt = (within >> 6) & 3;
    int lane = (within >> 1) & 31, reg = within & 1;
    int n = nb * 128 + nt * 8 + (lane >> 2);
    int c = chunk * 32 + kt * 8 + (lane & 3) + reg * 4;
    float v = W[(n * CIN + c) * 9 + s];
    asm("cvt.rna.tf32.f32 %0, %0;" : "+f"(v));
    g_wrf[idx] = __float_as_uint(v);
}

// ---------------- mma helpers ----------------
__device__ __forceinline__ void mma_tf32(float* d, const uint32_t* a, const uint32_t* b) {
    asm volatile(
        "mma.sync.aligned.m16n8k8.row.col.f32.tf32.tf32.f32 "
        "{%0,%1,%2,%3}, {%4,%5,%6,%7}, {%8,%9}, {%0,%1,%2,%3};"
        : "+f"(d[0]), "+f"(d[1]), "+f"(d[2]), "+f"(d[3])
        : "r"(a[0]), "r"(a[1]), "r"(a[2]), "r"(a[3]), "r"(b[0]), "r"(b[1]));
}
__device__ __forceinline__ void cp_async16(uint32_t sdst, const void* gsrc) {
    asm volatile("cp.async.cg.shared.global [%0], [%1], 16;" :: "r"(sdst), "l"(gsrc));
}
__device__ __forceinline__ uint32_t smem_u32(const void* p) {
    uint32_t a;
    asm("{ .reg .u64 t; cvta.to.shared.u64 t, %1; cvt.u32.u64 %0, t; }" : "=r"(a) : "l"(p));
    return a;
}

// ---------------- main ----------------
__global__ void __launch_bounds__(256, 2)
conv_main(const float* __restrict__ bias, float* __restrict__ out) {
    extern __shared__ char smem[];
    const uint32_t smem_b = smem_u32(smem);
    const int tid  = threadIdx.x;
    const int wid  = tid >> 5;
    const int lane = tid & 31;
    const int bb   = blockIdx.z;
    const int n0   = blockIdx.y * 128;
    const int q0   = blockIdx.x * 128;
    const int wm   = wid & 3;     // m-warp: 4 x 32 rows
    const int wn   = wid >> 2;    // n-warp: 2 x 64 cols

    const float* xpb = g_xpad + (long)bb * (CIN * CSTRIDE);

    float acc[2][8][4];
    #pragma unroll
    for (int i = 0; i < 2; i++)
        #pragma unroll
        for (int j = 0; j < 8; j++)
            #pragma unroll
            for (int k = 0; k < 4; k++) acc[i][j][k] = 0.0f;

    uint32_t au[4][4];   // staged A fragments (kt x 4 regs), warp wid stages mt=wid

    // A fragment gather for round params (s-chunk): lane l, fragment (mt=wid, kt)
    // a0=(r=l/4, c=l%4), a1=r+8, a2=c+4, a3=both  |  addr = (c0+kt*8+c)*CSTRIDE + q0+off + wid*16 + r
    #define LDA(c0, off)                                                              \
        do {                                                                          \
            const float* abase = xpb + (long)((c0) + (lane & 3)) * CSTRIDE            \
                                 + q0 + (off) + wid * 16 + (lane >> 2);               \
            _Pragma("unroll")                                                         \
            for (int kt = 0; kt < 4; kt++) {                                          \
                const float* p = abase + (long)kt * 8 * CSTRIDE;                      \
                au[kt][0] = __float_as_uint(__ldg(p));                                \
                au[kt][1] = __float_as_uint(__ldg(p + 8));                            \
                au[kt][2] = __float_as_uint(__ldg(p + 4 * CSTRIDE));                  \
                au[kt][3] = __float_as_uint(__ldg(p + 4 * CSTRIDE + 8));              \
            }                                                                         \
        } while (0)

    #define STA(bufofs)                                                               \
        do {                                                                          \
            _Pragma("unroll")                                                         \
            for (int kt = 0; kt < 4; kt++)                                            \
                *(uint4*)(smem + (bufofs) + ((wid * 4 + kt) * 32 + lane) * 16) =      \
                    make_uint4(au[kt][0], au[kt][1], au[kt][2], au[kt][3]);           \
        } while (0)

    #define LDB_ASYNC(s, chunk, bufofs)                                               \
        do {                                                                          \
            const uint32_t* src = g_wrf                                               \
                + ((size_t)(((s) * 2 + blockIdx.y) * 4 + (chunk))) * 4096 + tid * 4;  \
            uint32_t dst = smem_b + (bufofs) + SA_BYTES + tid * 16;                   \
            _Pragma("unroll")                                                         \
            for (int it = 0; it < 4; it++)                                            \
                cp_async16(dst + it * 4096, src + it * 1024);                         \
        } while (0)

    // ---- prologue: stage round 0 into buf 0 ----
    {
        LDB_ASYNC(0, 0, 0);
        asm volatile("cp.async.commit_group;" ::: "memory");
        LDA(0, 0);
        STA(0);
        asm volatile("cp.async.wait_group 0;" ::: "memory");
    }
    __syncthreads();

    for (int r = 0; r < NROUNDS; r++) {
        const int buf    = (r & 1) * BUF_BYTES;
        const int nbuf   = ((r + 1) & 1) * BUF_BYTES;

        if (r + 1 < NROUNDS) {
            const int s1 = (r + 1) >> 2, ch1 = (r + 1) & 3;
            const int off1 = (s1 / 3) * PW + (s1 % 3);
            LDB_ASYNC(s1, ch1, nbuf);
            asm volatile("cp.async.commit_group;" ::: "memory");
            LDA(ch1 * 32, off1);
        }

        // ---- compute round r ----
        const char* sAb = smem + buf;
        const char* sBb = smem + buf + SA_BYTES;
        #pragma unroll
        for (int kt = 0; kt < 4; kt++) {
            uint4 afr[2];
            #pragma unroll
            for (int mt = 0; mt < 2; mt++)
                afr[mt] = *(const uint4*)(sAb + (((wm * 2 + mt) * 4 + kt) * 32 + lane) * 16);
            uint2 bfr[8];
            #pragma unroll
            for (int nt = 0; nt < 8; nt++)
                bfr[nt] = *(const uint2*)(sBb + (((wn * 8 + nt) * 4 + kt) * 32 + lane) * 8);
            #pragma unroll
            for (int mt = 0; mt < 2; mt++)
                #pragma unroll
                for (int nt = 0; nt < 8; nt++)
                    mma_tf32(acc[mt][nt], (const uint32_t*)&afr[mt], (const uint32_t*)&bfr[nt]);
        }

        if (r + 1 < NROUNDS) {
            STA(nbuf);
            asm volatile("cp.async.wait_group 0;" ::: "memory");
        }
        __syncthreads();
    }

    // ---- epilogue ----
    const long obb = (long)bb * COUT * (HW * HW);
    #pragma unroll
    for (int nt = 0; nt < 8; nt++) {
        const int n = n0 + wn * 64 + nt * 8 + (lane & 3) * 2;
        const float bv0 = __ldg(bias + n);
        const float bv1 = __ldg(bias + n + 1);
        #pragma unroll
        for (int mt = 0; mt < 2; mt++) {
            const int m = q0 + wm * 32 + mt * 16 + (lane >> 2);
            // rows m (c0,c1) and m+8 (c2,c3)
            {
                const int h = m / PW, w = m % PW;
                if (h < HW && w < HW) {
                    const long o = obb + (long)n * (HW * HW) + h * HW + w;
                    out[o]             = acc[mt][nt][0] + bv0;
                    out[o + HW * HW]   = acc[mt][nt][1] + bv1;
                }
            }
            {
                const int m2 = m + 8;
                const int h = m2 / PW, w = m2 % PW;
                if (h < HW && w < HW) {
                    const long o = obb + (long)n * (HW * HW) + h * HW + w;
                    out[o]             = acc[mt][nt][2] + bv0;
                    out[o + HW * HW]   = acc[mt][nt][3] + bv1;
                }
            }
        }
    }
}

// ---------------- launch ----------------
extern "C" void kernel_launch(void* const* d_in, const int* in_sizes, int n_in,
                              void* d_out, int out_size) {
    const float* x  = (const float*)d_in[0];
    const float* W  = (const float*)d_in[1];
    const float* bi = (const float*)d_in[2];
    float* out      = (float*)d_out;

    cudaFuncSetAttribute(conv_main, cudaFuncAttributeMaxDynamicSharedMemorySize,
                         2 * BUF_BYTES);

    long pad_total = (long)BATCH * CIN * CSTRIDE;
    pad_kernel<<<(unsigned)((pad_total + 255) / 256), 256>>>(x);
    wrf_kernel<<<(9 * 2 * 4 * 4096 + 255) / 256, 256>>>(W);
    conv_main<<<dim3(MTILES, 2, BATCH), 256, 2 * BUF_BYTES>>>(bi, out);
}

// round 4
// speedup vs baseline: 4.1879x; 1.0916x over previous
#include <cuda_runtime.h>
#include <cstdint>

// ============================================================
// Conv2d 3x3 s1 p1: x(32,128,56,56)*W(256,128,3,3)+b -> (32,256,56,56)
// Shifted-GEMM conv on mma.sync.m16n8k8.tf32 (base sm_103 target).
// R4: chunk-outer / shift-inner. A staged once per 32-cin chunk WITH
// halo (376 px window) in smem [c][q] (q-stride 392 => conflict-free
// fragment LDS); all 9 shifts read the same staging at different
// offsets. CTA = 256 px x 128 couts, 512 threads (16 warps, warp
// tile 64x32). B in fragment order, double-buffered cp.async.
// ============================================================

#define HW        56
#define PW        58
#define CSTRIDE   3584
#define CIN       128
#define COUT      256
#define BATCH     32
#define MTILES    13            // 13*256 = 3328 >= last valid q 3303
#define NROUNDS   36            // 4 chunks * 9 shifts
#define AQ        392           // A smem q-stride (floats), ==8 mod 32
#define SA_BYTES  (32 * AQ * 4) // 50176
#define SB_BYTES  16384         // 128 couts x 32 cin x 4B
#define SMEM_TOTAL (SA_BYTES + 2 * SB_BYTES)

__device__ float    g_xpad[BATCH * CIN * CSTRIDE];   // tf32-rounded, zero-padded
__device__ uint32_t g_wrf[2 * 4 * 9 * 4096];         // W fragment order

// ---------------- prep ----------------
__global__ void zero_kernel() {
    long i = (long)blockIdx.x * blockDim.x + threadIdx.x;
    const long n4 = (long)BATCH * CIN * CSTRIDE / 4;
    if (i < n4) ((float4*)g_xpad)[i] = make_float4(0.f, 0.f, 0.f, 0.f);
}

__global__ void copy_kernel(const float* __restrict__ x) {
    int id = blockIdx.x * blockDim.x + threadIdx.x;   // 4096*56*14
    if (id >= 32 * 128 * 56 * 14) return;
    int f4 = id % 14;
    int h  = (id / 14) % 56;
    int bc = id / (14 * 56);
    float4 v = *(const float4*)(x + (long)bc * 3136 + h * 56 + f4 * 4);
    asm("cvt.rna.tf32.f32 %0, %0;" : "+f"(v.x));
    asm("cvt.rna.tf32.f32 %0, %0;" : "+f"(v.y));
    asm("cvt.rna.tf32.f32 %0, %0;" : "+f"(v.z));
    asm("cvt.rna.tf32.f32 %0, %0;" : "+f"(v.w));
    float* d = g_xpad + (long)bc * CSTRIDE + (h + 1) * PW + 1 + f4 * 4;
    d[0] = v.x; d[1] = v.y; d[2] = v.z; d[3] = v.w;
}

// g_wrf block = (nb*4 + chunk)*9 + s  (4096 u32 each)
// within = nt*256 + kt*64 + lane*2 + reg
// value = tf32(W[n][c][s]), n = nb*128+nt*8+lane/4, c = chunk*32+kt*8+(lane&3)+reg*4
__global__ void wrf_kernel(const float* __restrict__ W) {
    int idx = blockIdx.x * blockDim.x + threadIdx.x;
    if (idx >= 2 * 4 * 9 * 4096) return;
    int blk = idx >> 12, within = idx & 4095;
    int s = blk % 9, t = blk / 9;
    int chunk = t & 3, nb = t >> 2;
    int nt = within >> 8, kt = (within >> 6) & 3;
    int lane = (within >> 1) & 31, reg = within & 1;
    int n = nb * 128 + nt * 8 + (lane >> 2);
    int c = chunk * 32 + kt * 8 + (lane & 3) + reg * 4;
    float v = W[(n * CIN + c) * 9 + s];
    asm("cvt.rna.tf32.f32 %0, %0;" : "+f"(v));
    g_wrf[idx] = __float_as_uint(v);
}

// ---------------- helpers ----------------
__device__ __forceinline__ void mma_tf32(float* d, const uint32_t* a, const uint32_t* b) {
    asm volatile(
        "mma.sync.aligned.m16n8k8.row.col.f32.tf32.tf32.f32 "
        "{%0,%1,%2,%3}, {%4,%5,%6,%7}, {%8,%9}, {%0,%1,%2,%3};"
        : "+f"(d[0]), "+f"(d[1]), "+f"(d[2]), "+f"(d[3])
        : "r"(a[0]), "r"(a[1]), "r"(a[2]), "r"(a[3]), "r"(b[0]), "r"(b[1]));
}
__device__ __forceinline__ void cp_async16(uint32_t sdst, const void* gsrc) {
    asm volatile("cp.async.cg.shared.global [%0], [%1], 16;" :: "r"(sdst), "l"(gsrc));
}
__device__ __forceinline__ uint32_t smem_u32(const void* p) {
    uint32_t a;
    asm("{ .reg .u64 t; cvta.to.shared.u64 t, %1; cvt.u32.u64 %0, t; }" : "=r"(a) : "l"(p));
    return a;
}

// ---------------- main ----------------
__global__ void __launch_bounds__(512, 1)
conv_main(const float* __restrict__ bias, float* __restrict__ out) {
    extern __shared__ char smem[];
    const uint32_t smem_b = smem_u32(smem);
    const int tid  = threadIdx.x;
    const int lane = tid & 31;
    const int wid  = tid >> 5;
    const int wm   = wid & 3;          // 4 m-warps: 64 rows each
    const int wn   = wid >> 2;         // 4 n-warps: 32 couts each
    const int bb   = blockIdx.z;
    const int nb   = blockIdx.y;       // 0/1
    const int q0   = blockIdx.x * 256;

    const float* xpb = g_xpad + (long)bb * (CIN * CSTRIDE);

    float acc[4][4][4];
    #pragma unroll
    for (int i = 0; i < 4; i++)
        #pragma unroll
        for (int j = 0; j < 4; j++)
            #pragma unroll
            for (int k = 0; k < 4; k++) acc[i][j][k] = 0.0f;

    // A stage: 32 rows x 94 float4 (376 px window), cp.async
    #define STAGE_A(chunk)                                                         \
        do {                                                                       \
            const float* asrc = xpb + (long)((chunk) * 32) * CSTRIDE + q0;         \
            _Pragma("unroll")                                                      \
            for (int it = 0; it < 6; it++) {                                       \
                int id = it * 512 + tid;                                           \
                if (id < 32 * 94) {                                                \
                    int row = id / 94, col = id - row * 94;                        \
                    cp_async16(smem_b + (row * AQ + col * 4) * 4,                  \
                               asrc + (long)row * CSTRIDE + col * 4);              \
                }                                                                  \
            }                                                                      \
        } while (0)

    // B stage for round r into buffer bufsel (0/1): 16KB, 2 cp.async/thread
    #define STAGE_B(r, bufsel)                                                     \
        do {                                                                       \
            const uint32_t* src = g_wrf                                            \
                + ((size_t)((nb * 4 + ((r) / 9)) * 9 + ((r) % 9))) * 4096 + tid * 4; \
            uint32_t dst = smem_b + SA_BYTES + (bufsel) * SB_BYTES + tid * 16;     \
            cp_async16(dst, src);                                                  \
            cp_async16(dst + 8192, src + 2048);                                    \
        } while (0)

    // prologue
    STAGE_A(0);
    STAGE_B(0, 0);
    asm volatile("cp.async.commit_group;" ::: "memory");
    asm volatile("cp.async.wait_group 0;" ::: "memory");
    __syncthreads();

    for (int r = 0; r < NROUNDS; r++) {
        const int s     = r % 9;
        const int chunk = r / 9;
        const int buf   = r & 1;
        const int off   = (s / 3) * PW + (s % 3);

        if (r + 1 < NROUNDS) {
            STAGE_B(r + 1, buf ^ 1);
            asm volatile("cp.async.commit_group;" ::: "memory");
        }

        // ---- compute round (chunk, s) ----
        const char* sA = smem;
        const char* sB = smem + SA_BYTES + buf * SB_BYTES;
        const int qb = off + wm * 64 + (lane >> 2);
        #pragma unroll
        for (int kt = 0; kt < 4; kt++) {
            const float* arow = (const float*)sA + (kt * 8 + (lane & 3)) * AQ + qb;
            uint32_t afr[4][4];
            #pragma unroll
            for (int mt = 0; mt < 4; mt++) {
                const float* p = arow + mt * 16;
                afr[mt][0] = __float_as_uint(p[0]);
                afr[mt][1] = __float_as_uint(p[8]);
                afr[mt][2] = __float_as_uint(p[4 * AQ]);
                afr[mt][3] = __float_as_uint(p[4 * AQ + 8]);
            }
            uint2 bfr[4];
            #pragma unroll
            for (int nt = 0; nt < 4; nt++)
                bfr[nt] = *(const uint2*)(sB + (((wn * 4 + nt) * 4 + kt) * 32 + lane) * 8);
            #pragma unroll
            for (int mt = 0; mt < 4; mt++)
                #pragma unroll
                for (int nt = 0; nt < 4; nt++)
                    mma_tf32(acc[mt][nt], afr[mt], (const uint32_t*)&bfr[nt]);
        }

        if (s == 8 && chunk < 3) {
            __syncthreads();          // all warps done with A before restage
            STAGE_A(chunk + 1);
            asm volatile("cp.async.commit_group;" ::: "memory");
        }
        asm volatile("cp.async.wait_group 0;" ::: "memory");
        __syncthreads();
    }

    // ---- epilogue ----
    const long obb = (long)bb * COUT * (HW * HW);
    #pragma unroll
    for (int nt = 0; nt < 4; nt++) {
        const int n = nb * 128 + wn * 32 + nt * 8 + (lane & 3) * 2;
        const float bv0 = __ldg(bias + n);
        const float bv1 = __ldg(bias + n + 1);
        const long onb = obb + (long)n * (HW * HW);
        #pragma unroll
        for (int mt = 0; mt < 4; mt++) {
            const int m = q0 + wm * 64 + mt * 16 + (lane >> 2);
            {
                const int h = m / PW, w = m % PW;
                if (h < HW && w < HW) {
                    const long o = onb + h * HW + w;
                    out[o]           = acc[mt][nt][0] + bv0;
                    out[o + HW * HW] = acc[mt][nt][1] + bv1;
                }
            }
            {
                const int m2 = m + 8;
                const int h = m2 / PW, w = m2 % PW;
                if (h < HW && w < HW) {
                    const long o = onb + h * HW + w;
                    out[o]           = acc[mt][nt][2] + bv0;
                    out[o + HW * HW] = acc[mt][nt][3] + bv1;
                }
            }
        }
    }
}

// ---------------- launch ----------------
extern "C" void kernel_launch(void* const* d_in, const int* in_sizes, int n_in,
                              void* d_out, int out_size) {
    const float* x  = (const float*)d_in[0];
    const float* W  = (const float*)d_in[1];
    const float* bi = (const float*)d_in[2];
    float* out      = (float*)d_out;

    cudaFuncSetAttribute(conv_main, cudaFuncAttributeMaxDynamicSharedMemorySize,
                         SMEM_TOTAL);

    long n4 = (long)BATCH * CIN * CSTRIDE / 4;
    zero_kernel<<<(unsigned)((n4 + 255) / 256), 256>>>();
    copy_kernel<<<(32 * 128 * 56 * 14 + 255) / 256, 256>>>(x);
    wrf_kernel<<<(2 * 4 * 9 * 4096 + 255) / 256, 256>>>(W);
    conv_main<<<dim3(MTILES, 2, BATCH), 512, SMEM_TOTAL>>>(bi, out);
}

// round 6
// speedup vs baseline: 5.2502x; 1.2537x over previous
#include <cuda_runtime.h>
#include <cstdint>

// ============================================================
// Conv2d 3x3 s1 p1: x(32,128,56,56)*W(256,128,3,3)+b -> (32,256,56,56)
// Shifted-GEMM conv on mma.sync.m16n8k8.tf32 (base sm_103 target).
// R6: CTA = 128 px x 128 couts, 256 threads, 2 CTAs/SM.
// A staged once per 32-cin chunk with halo (248-px window, AQ=248).
// B fragment-ordered, 4-buffer cp.async ring, prefetch distance 2
// (ring must be >=4: writer hits (r+2)%NB, slow readers hold (r-1)%NB).
// ============================================================

#define HW        56
#define PW        58
#define CSTRIDE   3584
#define CIN       128
#define COUT      256
#define BATCH     32
#define MTILES    26            // 26*128 = 3328 >= last valid q 3245
#define NROUNDS   36            // 4 chunks * 9 shifts
#define AQ        248           // A smem q-stride (floats)
#define SA_BYTES  (32 * AQ * 4) // 31744
#define SB_BYTES  16384         // 128 couts x 32 cin x 4B
#define NB        4             // B ring depth
#define SMEM_TOTAL (SA_BYTES + NB * SB_BYTES)   // 97280

__device__ float    g_xpad[BATCH * CIN * CSTRIDE];   // tf32-rounded, zero-padded
__device__ uint32_t g_wrf[2 * 4 * 9 * 4096];         // W fragment order

// ---------------- prep ----------------
__global__ void zero_kernel() {
    long i = (long)blockIdx.x * blockDim.x + threadIdx.x;
    const long n4 = (long)BATCH * CIN * CSTRIDE / 4;
    if (i < n4) ((float4*)g_xpad)[i] = make_float4(0.f, 0.f, 0.f, 0.f);
}

__global__ void copy_kernel(const float* __restrict__ x) {
    int id = blockIdx.x * blockDim.x + threadIdx.x;   // 4096*56*14
    if (id >= 32 * 128 * 56 * 14) return;
    int f4 = id % 14;
    int h  = (id / 14) % 56;
    int bc = id / (14 * 56);
    float4 v = *(const float4*)(x + (long)bc * 3136 + h * 56 + f4 * 4);
    asm("cvt.rna.tf32.f32 %0, %0;" : "+f"(v.x));
    asm("cvt.rna.tf32.f32 %0, %0;" : "+f"(v.y));
    asm("cvt.rna.tf32.f32 %0, %0;" : "+f"(v.z));
    asm("cvt.rna.tf32.f32 %0, %0;" : "+f"(v.w));
    float* d = g_xpad + (long)bc * CSTRIDE + (h + 1) * PW + 1 + f4 * 4;
    d[0] = v.x; d[1] = v.y; d[2] = v.z; d[3] = v.w;
}

// g_wrf block = (nb*4 + chunk)*9 + s  (4096 u32 each)
// within = nt*256 + kt*64 + lane*2 + reg
// value = tf32(W[n][c][s]), n = nb*128+nt*8+lane/4, c = chunk*32+kt*8+(lane&3)+reg*4
__global__ void wrf_kernel(const float* __restrict__ W) {
    int idx = blockIdx.x * blockDim.x + threadIdx.x;
    if (idx >= 2 * 4 * 9 * 4096) return;
    int blk = idx >> 12, within = idx & 4095;
    int s = blk % 9, t = blk / 9;
    int chunk = t & 3, nb = t >> 2;
    int nt = within >> 8, kt = (within >> 6) & 3;
    int lane = (within >> 1) & 31, reg = within & 1;
    int n = nb * 128 + nt * 8 + (lane >> 2);
    int c = chunk * 32 + kt * 8 + (lane & 3) + reg * 4;
    float v = W[(n * CIN + c) * 9 + s];
    asm("cvt.rna.tf32.f32 %0, %0;" : "+f"(v));
    g_wrf[idx] = __float_as_uint(v);
}

// ---------------- helpers ----------------
__device__ __forceinline__ void mma_tf32(float* d, const uint32_t* a, const uint32_t* b) {
    asm volatile(
        "mma.sync.aligned.m16n8k8.row.col.f32.tf32.tf32.f32 "
        "{%0,%1,%2,%3}, {%4,%5,%6,%7}, {%8,%9}, {%0,%1,%2,%3};"
        : "+f"(d[0]), "+f"(d[1]), "+f"(d[2]), "+f"(d[3])
        : "r"(a[0]), "r"(a[1]), "r"(a[2]), "r"(a[3]), "r"(b[0]), "r"(b[1]));
}
__device__ __forceinline__ void cp_async16(uint32_t sdst, const void* gsrc) {
    asm volatile("cp.async.cg.shared.global [%0], [%1], 16;" :: "r"(sdst), "l"(gsrc));
}
__device__ __forceinline__ uint32_t smem_u32(const void* p) {
    uint32_t a;
    asm("{ .reg .u64 t; cvta.to.shared.u64 t, %1; cvt.u32.u64 %0, t; }" : "=r"(a) : "l"(p));
    return a;
}

// ---------------- main ----------------
__global__ void __launch_bounds__(256, 2)
conv_main(const float* __restrict__ bias, float* __restrict__ out) {
    extern __shared__ char smem[];
    const uint32_t smem_b = smem_u32(smem);
    const int tid  = threadIdx.x;
    const int lane = tid & 31;
    const int wid  = tid >> 5;
    const int wm   = wid & 3;          // 4 m-warps: 32 px each
    const int wn   = wid >> 2;         // 2 n-warps: 64 couts each
    const int bb   = blockIdx.z;
    const int nb   = blockIdx.y;       // 0/1
    const int q0   = blockIdx.x * 128;

    const float* xpb = g_xpad + (long)bb * (CIN * CSTRIDE);

    float acc[2][8][4];
    #pragma unroll
    for (int i = 0; i < 2; i++)
        #pragma unroll
        for (int j = 0; j < 8; j++)
            #pragma unroll
            for (int k = 0; k < 4; k++) acc[i][j][k] = 0.0f;

    // A stage: 32 rows x 62 float4 (248-px window)
    #define STAGE_A(chunk)                                                         \
        do {                                                                       \
            const float* asrc = xpb + (long)((chunk) * 32) * CSTRIDE + q0;         \
            _Pragma("unroll")                                                      \
            for (int it = 0; it < 8; it++) {                                       \
                int id = it * 256 + tid;                                           \
                if (id < 32 * 62) {                                                \
                    int row = id / 62, col = id - row * 62;                        \
                    cp_async16(smem_b + (row * AQ + col * 4) * 4,                  \
                               asrc + (long)row * CSTRIDE + col * 4);              \
                }                                                                  \
            }                                                                      \
        } while (0)

    // B stage for round r into ring buffer (r%NB): 16KB, 4 cp.async/thread
    #define STAGE_B(r)                                                             \
        do {                                                                       \
            const uint32_t* src = g_wrf                                            \
                + ((size_t)((nb * 4 + ((r) / 9)) * 9 + ((r) % 9))) * 4096 + tid * 4; \
            uint32_t dst = smem_b + SA_BYTES + ((r) % NB) * SB_BYTES + tid * 16;   \
            _Pragma("unroll")                                                      \
            for (int it = 0; it < 4; it++)                                         \
                cp_async16(dst + it * 4096, src + it * 1024);                      \
        } while (0)

    // prologue: A chunk 0, B rounds 0 and 1
    STAGE_A(0);
    STAGE_B(0);
    asm volatile("cp.async.commit_group;" ::: "memory");
    STAGE_B(1);
    asm volatile("cp.async.commit_group;" ::: "memory");

    for (int r = 0; r < NROUNDS; r++) {
        const int s     = r % 9;
        const int chunk = r / 9;
        const int off   = (s / 3) * PW + (s % 3);

        if (r + 2 < NROUNDS) {
            STAGE_B(r + 2);
            asm volatile("cp.async.commit_group;" ::: "memory");
            asm volatile("cp.async.wait_group 2;" ::: "memory");
        } else {
            asm volatile("cp.async.wait_group 0;" ::: "memory");
        }
        __syncthreads();

        // ---- compute round (chunk, s) ----
        const char* sB = smem + SA_BYTES + (r % NB) * SB_BYTES;
        const int qb = off + wm * 32 + (lane >> 2);
        #pragma unroll
        for (int kt = 0; kt < 4; kt++) {
            const float* arow = (const float*)smem + (kt * 8 + (lane & 3)) * AQ + qb;
            uint32_t afr[2][4];
            #pragma unroll
            for (int mt = 0; mt < 2; mt++) {
                const float* p = arow + mt * 16;
                afr[mt][0] = __float_as_uint(p[0]);
                afr[mt][1] = __float_as_uint(p[8]);
                afr[mt][2] = __float_as_uint(p[4 * AQ]);
                afr[mt][3] = __float_as_uint(p[4 * AQ + 8]);
            }
            uint2 bfr[8];
            #pragma unroll
            for (int nt = 0; nt < 8; nt++)
                bfr[nt] = *(const uint2*)(sB + (((wn * 8 + nt) * 4 + kt) * 32 + lane) * 8);
            #pragma unroll
            for (int mt = 0; mt < 2; mt++)
                #pragma unroll
                for (int nt = 0; nt < 8; nt++)
                    mma_tf32(acc[mt][nt], afr[mt], (const uint32_t*)&bfr[nt]);
        }

        if (s == 8 && chunk < 3) {
            __syncthreads();        // all warps done reading A
            STAGE_A(chunk + 1);
            asm volatile("cp.async.commit_group;" ::: "memory");
            asm volatile("cp.async.wait_group 0;" ::: "memory");
        }
    }

    // ---- epilogue ----
    const long obb = (long)bb * COUT * (HW * HW);
    #pragma unroll
    for (int nt = 0; nt < 8; nt++) {
        const int n = nb * 128 + wn * 64 + nt * 8 + (lane & 3) * 2;
        const float bv0 = __ldg(bias + n);
        const float bv1 = __ldg(bias + n + 1);
        const long onb = obb + (long)n * (HW * HW);
        #pragma unroll
        for (int mt = 0; mt < 2; mt++) {
            const int m = q0 + wm * 32 + mt * 16 + (lane >> 2);
            {
                const int h = m / PW, w = m % PW;
                if (h < HW && w < HW) {
                    const long o = onb + h * HW + w;
                    out[o]           = acc[mt][nt][0] + bv0;
                    out[o + HW * HW] = acc[mt][nt][1] + bv1;
                }
            }
            {
                const int m2 = m + 8;
                const int h = m2 / PW, w = m2 % PW;
                if (h < HW && w < HW) {
                    const long o = onb + h * HW + w;
                    out[o]           = acc[mt][nt][2] + bv0;
                    out[o + HW * HW] = acc[mt][nt][3] + bv1;
                }
            }
        }
    }
}

// ---------------- launch ----------------
extern "C" void kernel_launch(void* const* d_in, const int* in_sizes, int n_in,
                              void* d_out, int out_size) {
    const float* x  = (const float*)d_in[0];
    const float* W  = (const float*)d_in[1];
    const float* bi = (const float*)d_in[2];
    float* out      = (float*)d_out;

    cudaFuncSetAttribute(conv_main, cudaFuncAttributeMaxDynamicSharedMemorySize,
                         SMEM_TOTAL);

    long n4 = (long)BATCH * CIN * CSTRIDE / 4;
    zero_kernel<<<(unsigned)((n4 + 255) / 256), 256>>>();
    copy_kernel<<<(32 * 128 * 56 * 14 + 255) / 256, 256>>>(x);
    wrf_kernel<<<(2 * 4 * 9 * 4096 + 255) / 256, 256>>>(W);
    conv_main<<<dim3(MTILES, 2, BATCH), 256, SMEM_TOTAL>>>(bi, out);
}

// round 7
// speedup vs baseline: 5.3893x; 1.0265x over previous
#include <cuda_runtime.h>
#include <cstdint>

// ============================================================
// Conv2d 3x3 s1 p1: x(32,128,56,56)*W(256,128,3,3)+b -> (32,256,56,56)
// Shifted-GEMM conv on mma.sync.m16n8k8.tf32 (base sm_103 target).
// R7: B fragments repacked so each (kt,lane) reads its 8 uint2
// fragments as 4 conflict-free LDS.128 (was 32 LDS.64 per round,
// now 16 LDS.128). Border-only zeroing of the pad buffer.
// CTA = 128 px x 128 couts, 256 thr, 2 CTAs/SM; A halo window per
// 32-cin chunk (AQ=248); B 4-buffer cp.async ring, prefetch dist 2.
//
// g_wrf uint4 layout: u4 = ((p*4 + kt) * 32 + lane), p = nt-pair 0..7
//   word j: nt = p*2 + (j>>1), reg = j&1
//   value  = tf32(W[n][c][s]), n = nb*128 + nt*8 + lane/4,
//            c = chunk*32 + kt*8 + (lane&3) + reg*4
// Reader (warp wn): bfr pair p = wn*4 + c4  ->  nt_local = c4*2 + (j>>1).
// ============================================================

#define HW        56
#define PW        58
#define CSTRIDE   3584
#define CIN       128
#define COUT      256
#define BATCH     32
#define MTILES    26
#define NROUNDS   36
#define AQ        248
#define SA_BYTES  (32 * AQ * 4)
#define SB_BYTES  16384
#define NB        4
#define SMEM_TOTAL (SA_BYTES + NB * SB_BYTES)

__device__ float    g_xpad[BATCH * CIN * CSTRIDE];
__device__ uint32_t g_wrf[2 * 4 * 9 * 4096];

// ---------------- prep ----------------
__global__ void border_kernel() {
    int idx = blockIdx.x * blockDim.x + threadIdx.x;
    if (idx >= BATCH * CIN * 448) return;
    int i  = idx % 448;
    long bc = idx / 448;
    int pos;
    if (i < 58)       pos = i;
    else if (i < 116) pos = 57 * PW + (i - 58);
    else if (i < 228) {
        int j = i - 116;
        pos = (1 + (j >> 1)) * PW + ((j & 1) ? 57 : 0);
    } else            pos = PW * PW + (i - 228);
    g_xpad[bc * CSTRIDE + pos] = 0.0f;
}

__global__ void copy_kernel(const float* __restrict__ x) {
    int id = blockIdx.x * blockDim.x + threadIdx.x;
    if (id >= 32 * 128 * 56 * 14) return;
    int f4 = id % 14;
    int h  = (id / 14) % 56;
    int bc = id / (14 * 56);
    float4 v = *(const float4*)(x + (long)bc * 3136 + h * 56 + f4 * 4);
    asm("cvt.rna.tf32.f32 %0, %0;" : "+f"(v.x));
    asm("cvt.rna.tf32.f32 %0, %0;" : "+f"(v.y));
    asm("cvt.rna.tf32.f32 %0, %0;" : "+f"(v.z));
    asm("cvt.rna.tf32.f32 %0, %0;" : "+f"(v.w));
    float* d = g_xpad + (long)bc * CSTRIDE + (h + 1) * PW + 1 + f4 * 4;
    d[0] = v.x; d[1] = v.y; d[2] = v.z; d[3] = v.w;
}

__global__ void wrf_kernel(const float* __restrict__ W) {
    int idx = blockIdx.x * blockDim.x + threadIdx.x;
    if (idx >= 2 * 4 * 9 * 4096) return;
    int blk = idx >> 12, within = idx & 4095;
    int s = blk % 9, t = blk / 9;
    int chunk = t & 3, nb = t >> 2;
    int u4 = within >> 2, j = within & 3;
    int lane = u4 & 31, t4 = u4 >> 5;     // t4 = p*4 + kt
    int kt = t4 & 3, p = t4 >> 2;         // p = nt-pair 0..7
    int nt = p * 2 + (j >> 1), reg = j & 1;
    int n = nb * 128 + nt * 8 + (lane >> 2);
    int c = chunk * 32 + kt * 8 + (lane & 3) + reg * 4;
    float v = W[(n * CIN + c) * 9 + s];
    asm("cvt.rna.tf32.f32 %0, %0;" : "+f"(v));
    g_wrf[idx] = __float_as_uint(v);
}

// ---------------- helpers ----------------
__device__ __forceinline__ void mma_tf32(float* d, const uint32_t* a, const uint32_t* b) {
    asm volatile(
        "mma.sync.aligned.m16n8k8.row.col.f32.tf32.tf32.f32 "
        "{%0,%1,%2,%3}, {%4,%5,%6,%7}, {%8,%9}, {%0,%1,%2,%3};"
        : "+f"(d[0]), "+f"(d[1]), "+f"(d[2]), "+f"(d[3])
        : "r"(a[0]), "r"(a[1]), "r"(a[2]), "r"(a[3]), "r"(b[0]), "r"(b[1]));
}
__device__ __forceinline__ void cp_async16(uint32_t sdst, const void* gsrc) {
    asm volatile("cp.async.cg.shared.global [%0], [%1], 16;" :: "r"(sdst), "l"(gsrc));
}
__device__ __forceinline__ uint32_t smem_u32(const void* p) {
    uint32_t a;
    asm("{ .reg .u64 t; cvta.to.shared.u64 t, %1; cvt.u32.u64 %0, t; }" : "=r"(a) : "l"(p));
    return a;
}

// ---------------- main ----------------
__global__ void __launch_bounds__(256, 2)
conv_main(const float* __restrict__ bias, float* __restrict__ out) {
    extern __shared__ char smem[];
    const uint32_t smem_b = smem_u32(smem);
    const int tid  = threadIdx.x;
    const int lane = tid & 31;
    const int wid  = tid >> 5;
    const int wm   = wid & 3;
    const int wn   = wid >> 2;
    const int bb   = blockIdx.z;
    const int nb   = blockIdx.y;
    const int q0   = blockIdx.x * 128;

    const float* xpb = g_xpad + (long)bb * (CIN * CSTRIDE);

    float acc[2][8][4];
    #pragma unroll
    for (int i = 0; i < 2; i++)
        #pragma unroll
        for (int j = 0; j < 8; j++)
            #pragma unroll
            for (int k = 0; k < 4; k++) acc[i][j][k] = 0.0f;

    #define STAGE_A(chunk)                                                         \
        do {                                                                       \
            const float* asrc = xpb + (long)((chunk) * 32) * CSTRIDE + q0;         \
            _Pragma("unroll")                                                      \
            for (int it = 0; it < 8; it++) {                                       \
                int id = it * 256 + tid;                                           \
                if (id < 32 * 62) {                                                \
                    int row = id / 62, col = id - row * 62;                        \
                    cp_async16(smem_b + (row * AQ + col * 4) * 4,                  \
                               asrc + (long)row * CSTRIDE + col * 4);              \
                }                                                                  \
            }                                                                      \
        } while (0)

    #define STAGE_B(r)                                                             \
        do {                                                                       \
            const uint32_t* src = g_wrf                                            \
                + ((size_t)((nb * 4 + ((r) / 9)) * 9 + ((r) % 9))) * 4096 + tid * 4; \
            uint32_t dst = smem_b + SA_BYTES + ((r) % NB) * SB_BYTES + tid * 16;   \
            _Pragma("unroll")                                                      \
            for (int it = 0; it < 4; it++)                                         \
                cp_async16(dst + it * 4096, src + it * 1024);                      \
        } while (0)

    STAGE_A(0);
    STAGE_B(0);
    asm volatile("cp.async.commit_group;" ::: "memory");
    STAGE_B(1);
    asm volatile("cp.async.commit_group;" ::: "memory");

    for (int r = 0; r < NROUNDS; r++) {
        const int s     = r % 9;
        const int chunk = r / 9;
        const int off   = (s / 3) * PW + (s % 3);

        if (r + 2 < NROUNDS) {
            STAGE_B(r + 2);
            asm volatile("cp.async.commit_group;" ::: "memory");
            asm volatile("cp.async.wait_group 2;" ::: "memory");
        } else {
            asm volatile("cp.async.wait_group 0;" ::: "memory");
        }
        __syncthreads();

        const uint4* sB4 = (const uint4*)(smem + SA_BYTES + (r % NB) * SB_BYTES);
        const int qb = off + wm * 32 + (lane >> 2);
        #pragma unroll
        for (int kt = 0; kt < 4; kt++) {
            const float* arow = (const float*)smem + (kt * 8 + (lane & 3)) * AQ + qb;
            uint32_t afr[2][4];
            #pragma unroll
            for (int mt = 0; mt < 2; mt++) {
                const float* p = arow + mt * 16;
                afr[mt][0] = __float_as_uint(p[0]);
                afr[mt][1] = __float_as_uint(p[8]);
                afr[mt][2] = __float_as_uint(p[4 * AQ]);
                afr[mt][3] = __float_as_uint(p[4 * AQ + 8]);
            }
            uint4 bfr4[4];
            #pragma unroll
            for (int c4 = 0; c4 < 4; c4++)
                bfr4[c4] = sB4[((wn * 4 + c4) * 4 + kt) * 32 + lane];
            #pragma unroll
            for (int mt = 0; mt < 2; mt++)
                #pragma unroll
                for (int c4 = 0; c4 < 4; c4++) {
                    mma_tf32(acc[mt][c4 * 2],     afr[mt], (const uint32_t*)&bfr4[c4]);
                    mma_tf32(acc[mt][c4 * 2 + 1], afr[mt], ((const uint32_t*)&bfr4[c4]) + 2);
                }
        }

        if (s == 8 && chunk < 3) {
            __syncthreads();
            STAGE_A(chunk + 1);
            asm volatile("cp.async.commit_group;" ::: "memory");
            asm volatile("cp.async.wait_group 0;" ::: "memory");
        }
    }

    // ---- epilogue ----
    const long obb = (long)bb * COUT * (HW * HW);
    #pragma unroll
    for (int nt = 0; nt < 8; nt++) {
        const int n = nb * 128 + wn * 64 + nt * 8 + (lane & 3) * 2;
        const float bv0 = __ldg(bias + n);
        const float bv1 = __ldg(bias + n + 1);
        const long onb = obb + (long)n * (HW * HW);
        #pragma unroll
        for (int mt = 0; mt < 2; mt++) {
            const int m = q0 + wm * 32 + mt * 16 + (lane >> 2);
            {
                const int h = m / PW, w = m % PW;
                if (h < HW && w < HW) {
                    const long o = onb + h * HW + w;
                    out[o]           = acc[mt][nt][0] + bv0;
                    out[o + HW * HW] = acc[mt][nt][1] + bv1;
                }
            }
            {
                const int m2 = m + 8;
                const int h = m2 / PW, w = m2 % PW;
                if (h < HW && w < HW) {
                    const long o = onb + h * HW + w;
                    out[o]           = acc[mt][nt][2] + bv0;
                    out[o + HW * HW] = acc[mt][nt][3] + bv1;
                }
            }
        }
    }
}

// ---------------- launch ----------------
extern "C" void kernel_launch(void* const* d_in, const int* in_sizes, int n_in,
                              void* d_out, int out_size) {
    const float* x  = (const float*)d_in[0];
    const float* W  = (const float*)d_in[1];
    const float* bi = (const float*)d_in[2];
    float* out      = (float*)d_out;

    cudaFuncSetAttribute(conv_main, cudaFuncAttributeMaxDynamicSharedMemorySize,
                         SMEM_TOTAL);

    border_kernel<<<(BATCH * CIN * 448 + 255) / 256, 256>>>();
    copy_kernel<<<(32 * 128 * 56 * 14 + 255) / 256, 256>>>(x);
    wrf_kernel<<<(2 * 4 * 9 * 4096 + 255) / 256, 256>>>(W);
    conv_main<<<dim3(MTILES, 2, BATCH), 256, SMEM_TOTAL>>>(bi, out);
}

// round 8
// speedup vs baseline: 8.1378x; 1.5100x over previous
#include <cuda_runtime.h>
#include <cuda_fp16.h>
#include <cstdint>

// ============================================================
// Conv2d 3x3 s1 p1: x(32,128,56,56)*W(256,128,3,3)+b -> (32,256,56,56)
// Shifted-GEMM conv on mma.sync.m16n8k16.f32.f16.f16.f32.
// fp16 keeps tf32-equivalent precision (10 explicit mantissa bits,
// inputs well in range) at 2x MAC/instr.
// x prepacked as half2 cin-pairs: g_xpadh[b][c2][q] (zero-padded 58x58).
// W prepacked in mma fragment order as half2, uint4-packed for LDS.128.
// CTA = 128 px x 128 couts, 256 thr, 2 CTAs/SM.
// A double-buffered per 32-cin chunk (halo window 248 px, AQ=248),
// B 4-buffer cp.async ring, prefetch distance 2.
// ============================================================

#define HW        56
#define PW        58
#define CSTRIDE   3584          // half2 units per (b,c2) slice
#define CIN       128
#define COUT      256
#define BATCH     32
#define MTILES    26
#define NROUNDS   36            // 4 chunks * 9 shifts
#define AQ        248           // A smem q-stride (half2 units)
#define SA_BYTES  (16 * AQ * 4) // 15872 per A buffer (16 c2-rows)
#define SB_BYTES  8192          // 128 couts x 32 cin x 2B
#define NB        4
#define SMEM_TOTAL (2 * SA_BYTES + NB * SB_BYTES)   // 64512

__device__ __half2  g_xpadh[BATCH * 64 * CSTRIDE];   // ~29.4 MB
__device__ uint32_t g_wrfh[2 * 4 * 9 * 2048];        // W fragment order (half2)

#define N_COPY (32 * 64 * 56 * 14)
#define N_BORD (32 * 64 * 448)
#define N_WRF  (2 * 4 * 9 * 2048)

// ---------------- fused prep ----------------
// range 1: interior copy  (x float -> half2 cin-pair, shifted +1,+1)
// range 2: border + slack zeroing (half2 domain)
// range 3: W -> fragment-order half2
// g_wrfh: block = (nb*4+chunk)*9+s, u4 = ((p*2+kt)*32+lane), word j:
//   nt = p*2+(j>>1), reg = j&1
//   half2 = ( W[n][c], W[n][c+1] ),  n = nb*128+nt*8+lane/4,
//   c = chunk*32 + kt*16 + (lane&3)*2 + reg*8
__global__ void prep_kernel(const float* __restrict__ x, const float* __restrict__ W) {
    int id = blockIdx.x * blockDim.x + threadIdx.x;
    if (id < N_COPY) {
        int f4  = id % 14;
        int h   = (id / 14) % 56;
        int bc2 = id / (14 * 56);          // b*64 + c2
        const float* p0 = x + ((long)bc2 * 2) * 3136 + h * 56 + f4 * 4;
        float4 v0 = *(const float4*)p0;
        float4 v1 = *(const float4*)(p0 + 3136);
        __half2* d = g_xpadh + (long)bc2 * CSTRIDE + (h + 1) * PW + 1 + f4 * 4;
        d[0] = __floats2half2_rn(v0.x, v1.x);
        d[1] = __floats2half2_rn(v0.y, v1.y);
        d[2] = __floats2half2_rn(v0.z, v1.z);
        d[3] = __floats2half2_rn(v0.w, v1.w);
    } else if (id < N_COPY + N_BORD) {
        int t = id - N_COPY;
        int i = t % 448;
        long bc2 = t / 448;
        int pos;
        if (i < 58)       pos = i;
        else if (i < 116) pos = 57 * PW + (i - 58);
        else if (i < 228) {
            int j = i - 116;
            pos = (1 + (j >> 1)) * PW + ((j & 1) ? 57 : 0);
        } else            pos = PW * PW + (i - 228);
        g_xpadh[bc2 * CSTRIDE + pos] = __floats2half2_rn(0.f, 0.f);
    } else if (id < N_COPY + N_BORD + N_WRF) {
        int idx3 = id - N_COPY - N_BORD;
        int blk = idx3 >> 11, within = idx3 & 2047;
        int s = blk % 9, t = blk / 9;
        int chunk = t & 3, nb = t >> 2;
        int u4 = within >> 2, j = within & 3;
        int lane = u4 & 31, t2 = u4 >> 5;
        int kt = t2 & 1, p = t2 >> 1;
        int nt = p * 2 + (j >> 1), reg = j & 1;
        int n = nb * 128 + nt * 8 + (lane >> 2);
        int c = chunk * 32 + kt * 16 + (lane & 3) * 2 + reg * 8;
        __half2 hv = __floats2half2_rn(W[(n * CIN + c) * 9 + s],
                                       W[(n * CIN + c + 1) * 9 + s]);
        g_wrfh[idx3] = *(uint32_t*)&hv;
    }
}

// ---------------- helpers ----------------
__device__ __forceinline__ void mma_f16(float* d, const uint32_t* a, const uint32_t* b) {
    asm volatile(
        "mma.sync.aligned.m16n8k16.row.col.f32.f16.f16.f32 "
        "{%0,%1,%2,%3}, {%4,%5,%6,%7}, {%8,%9}, {%0,%1,%2,%3};"
        : "+f"(d[0]), "+f"(d[1]), "+f"(d[2]), "+f"(d[3])
        : "r"(a[0]), "r"(a[1]), "r"(a[2]), "r"(a[3]), "r"(b[0]), "r"(b[1]));
}
__device__ __forceinline__ void cp_async16(uint32_t sdst, const void* gsrc) {
    asm volatile("cp.async.cg.shared.global [%0], [%1], 16;" :: "r"(sdst), "l"(gsrc));
}
__device__ __forceinline__ uint32_t smem_u32(const void* p) {
    uint32_t a;
    asm("{ .reg .u64 t; cvta.to.shared.u64 t, %1; cvt.u32.u64 %0, t; }" : "=r"(a) : "l"(p));
    return a;
}

// ---------------- main ----------------
__global__ void __launch_bounds__(256, 2)
conv_main(const float* __restrict__ bias, float* __restrict__ out) {
    extern __shared__ char smem[];
    const uint32_t smem_b = smem_u32(smem);
    const int tid  = threadIdx.x;
    const int lane = tid & 31;
    const int wid  = tid >> 5;
    const int wm   = wid & 3;          // 4 m-warps: 32 px each
    const int wn   = wid >> 2;         // 2 n-warps: 64 couts each
    const int bb   = blockIdx.z;
    const int nb   = blockIdx.y;       // 0/1
    const int q0   = blockIdx.x * 128;

    const __half2* xpbh = g_xpadh + (long)bb * 64 * CSTRIDE;

    float acc[2][8][4];
    #pragma unroll
    for (int i = 0; i < 2; i++)
        #pragma unroll
        for (int j = 0; j < 8; j++)
            #pragma unroll
            for (int k = 0; k < 4; k++) acc[i][j][k] = 0.0f;

    // A stage: 16 c2-rows x 62 x 16B (248 half2 window) into buffer sel
    #define STAGE_A(chunk, sel)                                                    \
        do {                                                                       \
            const __half2* asrc = xpbh + (long)((chunk) * 16) * CSTRIDE + q0;      \
            _Pragma("unroll")                                                      \
            for (int it = 0; it < 4; it++) {                                       \
                int aid = it * 256 + tid;                                          \
                if (aid < 16 * 62) {                                               \
                    int row = aid / 62, col = aid - row * 62;                      \
                    cp_async16(smem_b + (sel) * SA_BYTES + (row * AQ + col * 4) * 4, \
                               asrc + (long)row * CSTRIDE + col * 4);              \
                }                                                                  \
            }                                                                      \
        } while (0)

    // B stage for round r into ring buffer (r%NB): 8KB, 2 cp.async/thread
    #define STAGE_B(r)                                                             \
        do {                                                                       \
            const uint32_t* src = g_wrfh                                           \
                + ((size_t)((nb * 4 + ((r) / 9)) * 9 + ((r) % 9))) * 2048 + tid * 4; \
            uint32_t dst = smem_b + 2 * SA_BYTES + ((r) % NB) * SB_BYTES + tid * 16; \
            cp_async16(dst, src);                                                  \
            cp_async16(dst + 4096, src + 1024);                                    \
        } while (0)

    // prologue: A chunk 0 -> buf 0, B rounds 0 and 1
    STAGE_A(0, 0);
    STAGE_B(0);
    asm volatile("cp.async.commit_group;" ::: "memory");
    STAGE_B(1);
    asm volatile("cp.async.commit_group;" ::: "memory");

    for (int r = 0; r < NROUNDS; r++) {
        const int s     = r % 9;
        const int chunk = r / 9;
        const int off   = (s / 3) * PW + (s % 3);

        if (r + 2 < NROUNDS) {
            STAGE_B(r + 2);
            // A for next chunk, staged at s==1 (alias-safe vs s==0 readers)
            if (s == 1 && chunk < 3) STAGE_A(chunk + 1, (chunk + 1) & 1);
            asm volatile("cp.async.commit_group;" ::: "memory");
            asm volatile("cp.async.wait_group 2;" ::: "memory");
        } else {
            asm volatile("cp.async.wait_group 0;" ::: "memory");
        }
        __syncthreads();

        // ---- compute round (chunk, s) ----
        const uint32_t* sA = (const uint32_t*)(smem + (chunk & 1) * SA_BYTES);
        const uint4* sB4 = (const uint4*)(smem + 2 * SA_BYTES + (r % NB) * SB_BYTES);
        const int qb = off + wm * 32 + (lane >> 2);
        #pragma unroll
        for (int kt = 0; kt < 2; kt++) {
            const uint32_t* arow = sA + (kt * 8 + (lane & 3)) * AQ;
            uint32_t afr[2][4];
            #pragma unroll
            for (int mt = 0; mt < 2; mt++) {
                const int q = qb + mt * 16;
                afr[mt][0] = arow[q];
                afr[mt][1] = arow[q + 8];
                afr[mt][2] = arow[4 * AQ + q];
                afr[mt][3] = arow[4 * AQ + q + 8];
            }
            uint4 bfr[4];
            #pragma unroll
            for (int c4 = 0; c4 < 4; c4++)
                bfr[c4] = sB4[((wn * 4 + c4) * 2 + kt) * 32 + lane];
            #pragma unroll
            for (int mt = 0; mt < 2; mt++)
                #pragma unroll
                for (int c4 = 0; c4 < 4; c4++) {
                    mma_f16(acc[mt][c4 * 2],     afr[mt], (const uint32_t*)&bfr[c4]);
                    mma_f16(acc[mt][c4 * 2 + 1], afr[mt], ((const uint32_t*)&bfr[c4]) + 2);
                }
        }
    }

    // ---- epilogue (C fragment layout identical to k8 path) ----
    const long obb = (long)bb * COUT * (HW * HW);
    #pragma unroll
    for (int nt = 0; nt < 8; nt++) {
        const int n = nb * 128 + wn * 64 + nt * 8 + (lane & 3) * 2;
        const float bv0 = __ldg(bias + n);
        const float bv1 = __ldg(bias + n + 1);
        const long onb = obb + (long)n * (HW * HW);
        #pragma unroll
        for (int mt = 0; mt < 2; mt++) {
            const int m = q0 + wm * 32 + mt * 16 + (lane >> 2);
            {
                const int h = m / PW, w = m % PW;
                if (h < HW && w < HW) {
                    const long o = onb + h * HW + w;
                    out[o]           = acc[mt][nt][0] + bv0;
                    out[o + HW * HW] = acc[mt][nt][1] + bv1;
                }
            }
            {
                const int m2 = m + 8;
                const int h = m2 / PW, w = m2 % PW;
                if (h < HW && w < HW) {
                    const long o = onb + h * HW + w;
                    out[o]           = acc[mt][nt][2] + bv0;
                    out[o + HW * HW] = acc[mt][nt][3] + bv1;
                }
            }
        }
    }
}

// ---------------- launch ----------------
extern "C" void kernel_launch(void* const* d_in, const int* in_sizes, int n_in,
                              void* d_out, int out_size) {
    const float* x  = (const float*)d_in[0];
    const float* W  = (const float*)d_in[1];
    const float* bi = (const float*)d_in[2];
    float* out      = (float*)d_out;

    cudaFuncSetAttribute(conv_main, cudaFuncAttributeMaxDynamicSharedMemorySize,
                         SMEM_TOTAL);

    const int prep_total = N_COPY + N_BORD + N_WRF;
    prep_kernel<<<(prep_total + 255) / 256, 256>>>(x, W);
    conv_main<<<dim3(MTILES, 2, BATCH), 256, SMEM_TOTAL>>>(bi, out);
}

// round 9
// speedup vs baseline: 9.1657x; 1.1263x over previous
#include <cuda_runtime.h>
#include <cuda_fp16.h>
#include <cstdint>

// ============================================================
// Conv2d 3x3 s1 p1: x(32,128,56,56)*W(256,128,3,3)+b -> (32,256,56,56)
// Shifted-GEMM conv on mma.sync.m16n8k16.f32.f16.f16.f32.
// R9: pair-rounds — one barrier + one cp.async group per TWO shifts
// (18 sync windows, was 36). B staged in 16KB pair-buffers, ring of 3
// (writer (pr+1)%3, readers pr%3, laggards (pr-1)%3: no alias, so
// staging may be issued before the top-of-pair barrier). A per-chunk
// halo window (AQ=248), double-buffered; chunk c staged pairs ahead.
// CTA = 128 px x 128 couts, 256 thr, 2 CTAs/SM.
// ============================================================

#define HW        56
#define PW        58
#define CSTRIDE   3584          // half2 units per (b,c2) slice
#define CIN       128
#define COUT      256
#define BATCH     32
#define MTILES    26
#define NPAIRS    18            // 36 shift-rounds as 18 pairs
#define AQ        248           // A smem q-stride (half2 units)
#define SA_BYTES  (16 * AQ * 4) // 15872 per A buffer
#define ABUFS     (2 * SA_BYTES)
#define SBP_BYTES 16384         // B pair buffer (2 rounds x 8KB)
#define SMEM_TOTAL (ABUFS + 3 * SBP_BYTES)   // 80896

__device__ __half2  g_xpadh[BATCH * 64 * CSTRIDE];
__device__ uint32_t g_wrfh[2 * 4 * 9 * 2048];

#define N_COPY (32 * 64 * 56 * 14)
#define N_BORD (32 * 64 * 448)
#define N_WRF  (2 * 4 * 9 * 2048)

// ---------------- fused prep (identical to R8) ----------------
__global__ void prep_kernel(const float* __restrict__ x, const float* __restrict__ W) {
    int id = blockIdx.x * blockDim.x + threadIdx.x;
    if (id < N_COPY) {
        int f4  = id % 14;
        int h   = (id / 14) % 56;
        int bc2 = id / (14 * 56);
        const float* p0 = x + ((long)bc2 * 2) * 3136 + h * 56 + f4 * 4;
        float4 v0 = *(const float4*)p0;
        float4 v1 = *(const float4*)(p0 + 3136);
        __half2* d = g_xpadh + (long)bc2 * CSTRIDE + (h + 1) * PW + 1 + f4 * 4;
        d[0] = __floats2half2_rn(v0.x, v1.x);
        d[1] = __floats2half2_rn(v0.y, v1.y);
        d[2] = __floats2half2_rn(v0.z, v1.z);
        d[3] = __floats2half2_rn(v0.w, v1.w);
    } else if (id < N_COPY + N_BORD) {
        int t = id - N_COPY;
        int i = t % 448;
        long bc2 = t / 448;
        int pos;
        if (i < 58)       pos = i;
        else if (i < 116) pos = 57 * PW + (i - 58);
        else if (i < 228) {
            int j = i - 116;
            pos = (1 + (j >> 1)) * PW + ((j & 1) ? 57 : 0);
        } else            pos = PW * PW + (i - 228);
        g_xpadh[bc2 * CSTRIDE + pos] = __floats2half2_rn(0.f, 0.f);
    } else if (id < N_COPY + N_BORD + N_WRF) {
        int idx3 = id - N_COPY - N_BORD;
        int blk = idx3 >> 11, within = idx3 & 2047;
        int s = blk % 9, t = blk / 9;
        int chunk = t & 3, nb = t >> 2;
        int u4 = within >> 2, j = within & 3;
        int lane = u4 & 31, t2 = u4 >> 5;
        int kt = t2 & 1, p = t2 >> 1;
        int nt = p * 2 + (j >> 1), reg = j & 1;
        int n = nb * 128 + nt * 8 + (lane >> 2);
        int c = chunk * 32 + kt * 16 + (lane & 3) * 2 + reg * 8;
        __half2 hv = __floats2half2_rn(W[(n * CIN + c) * 9 + s],
                                       W[(n * CIN + c + 1) * 9 + s]);
        g_wrfh[idx3] = *(uint32_t*)&hv;
    }
}

// ---------------- helpers ----------------
__device__ __forceinline__ void mma_f16(float* d, const uint32_t* a, const uint32_t* b) {
    asm volatile(
        "mma.sync.aligned.m16n8k16.row.col.f32.f16.f16.f32 "
        "{%0,%1,%2,%3}, {%4,%5,%6,%7}, {%8,%9}, {%0,%1,%2,%3};"
        : "+f"(d[0]), "+f"(d[1]), "+f"(d[2]), "+f"(d[3])
        : "r"(a[0]), "r"(a[1]), "r"(a[2]), "r"(a[3]), "r"(b[0]), "r"(b[1]));
}
__device__ __forceinline__ void cp_async16(uint32_t sdst, const void* gsrc) {
    asm volatile("cp.async.cg.shared.global [%0], [%1], 16;" :: "r"(sdst), "l"(gsrc));
}
__device__ __forceinline__ uint32_t smem_u32(const void* p) {
    uint32_t a;
    asm("{ .reg .u64 t; cvta.to.shared.u64 t, %1; cvt.u32.u64 %0, t; }" : "=r"(a) : "l"(p));
    return a;
}
__device__ __forceinline__ int chunk_of(int r) {
    return (r >= 27) ? 3 : (r >= 18) ? 2 : (r >= 9) ? 1 : 0;
}

// one shift-round of MMA work
__device__ __forceinline__ void compute_round(
    const char* smem, int chunk, int off, int bofs,
    int wm, int wn, int lane, float acc[2][8][4])
{
    const uint32_t* sA = (const uint32_t*)(smem + (chunk & 1) * SA_BYTES);
    const uint4* sB4 = (const uint4*)(smem + ABUFS + bofs);
    const int qb = off + wm * 32 + (lane >> 2);
    #pragma unroll
    for (int kt = 0; kt < 2; kt++) {
        const uint32_t* arow = sA + (kt * 8 + (lane & 3)) * AQ;
        uint32_t afr[2][4];
        #pragma unroll
        for (int mt = 0; mt < 2; mt++) {
            const int q = qb + mt * 16;
            afr[mt][0] = arow[q];
            afr[mt][1] = arow[q + 8];
            afr[mt][2] = arow[4 * AQ + q];
            afr[mt][3] = arow[4 * AQ + q + 8];
        }
        uint4 bfr[4];
        #pragma unroll
        for (int c4 = 0; c4 < 4; c4++)
            bfr[c4] = sB4[((wn * 4 + c4) * 2 + kt) * 32 + lane];
        #pragma unroll
        for (int mt = 0; mt < 2; mt++)
            #pragma unroll
            for (int c4 = 0; c4 < 4; c4++) {
                mma_f16(acc[mt][c4 * 2],     afr[mt], (const uint32_t*)&bfr[c4]);
                mma_f16(acc[mt][c4 * 2 + 1], afr[mt], ((const uint32_t*)&bfr[c4]) + 2);
            }
    }
}

// ---------------- main ----------------
__global__ void __launch_bounds__(256, 2)
conv_main(const float* __restrict__ bias, float* __restrict__ out) {
    extern __shared__ char smem[];
    const uint32_t smem_b = smem_u32(smem);
    const int tid  = threadIdx.x;
    const int lane = tid & 31;
    const int wid  = tid >> 5;
    const int wm   = wid & 3;          // 4 m-warps: 32 px each
    const int wn   = wid >> 2;         // 2 n-warps: 64 couts each
    const int bb   = blockIdx.z;
    const int nb   = blockIdx.y;       // 0/1
    const int q0   = blockIdx.x * 128;

    const __half2* xpbh = g_xpadh + (long)bb * 64 * CSTRIDE;

    float acc[2][8][4];
    #pragma unroll
    for (int i = 0; i < 2; i++)
        #pragma unroll
        for (int j = 0; j < 8; j++)
            #pragma unroll
            for (int k = 0; k < 4; k++) acc[i][j][k] = 0.0f;

    // A stage: 16 c2-rows x 62 x 16B into buffer sel
    #define STAGE_A(chunk, sel)                                                    \
        do {                                                                       \
            const __half2* asrc = xpbh + (long)((chunk) * 16) * CSTRIDE + q0;      \
            _Pragma("unroll")                                                      \
            for (int it = 0; it < 4; it++) {                                       \
                int aid = it * 256 + tid;                                          \
                if (aid < 16 * 62) {                                               \
                    int row = aid / 62, col = aid - row * 62;                      \
                    cp_async16(smem_b + (sel) * SA_BYTES + (row * AQ + col * 4) * 4, \
                               asrc + (long)row * CSTRIDE + col * 4);              \
                }                                                                  \
            }                                                                      \
        } while (0)

    // stage one shift-round r into pair buffer (r>>1)%3, half (r&1)
    #define STAGE_B1(r)                                                            \
        do {                                                                       \
            const int ch = chunk_of(r), sh = (r) - 9 * ch;                         \
            const uint32_t* src = g_wrfh                                           \
                + ((size_t)((nb * 4 + ch) * 9 + sh)) * 2048 + tid * 4;             \
            uint32_t dst = smem_b + ABUFS + (((r) >> 1) % 3) * SBP_BYTES           \
                           + ((r) & 1) * 8192 + tid * 16;                          \
            cp_async16(dst, src);                                                  \
            cp_async16(dst + 4096, src + 1024);                                    \
        } while (0)

    // prologue: A chunk 0 -> buf 0, B pair 0 (rounds 0,1)
    STAGE_A(0, 0);
    STAGE_B1(0);
    STAGE_B1(1);
    asm volatile("cp.async.commit_group;" ::: "memory");

    for (int pr = 0; pr < NPAIRS; pr++) {
        const int r0 = 2 * pr, r1 = r0 + 1;

        if (pr + 1 < NPAIRS) {
            STAGE_B1(r0 + 2);
            STAGE_B1(r0 + 3);
            // A chunk staging: pairs 2,6,11 -> chunks 1,2,3 (buffers 1,0,1).
            // Safety: writer at top of pair P overlaps at most pair P-1 compute
            // (barrier at top of P-1 already passed by all); target buffer's
            // previous readers finished >= 1 pair earlier in every case.
            if (pr == 2)       STAGE_A(1, 1);
            else if (pr == 6)  STAGE_A(2, 0);
            else if (pr == 11) STAGE_A(3, 1);
            asm volatile("cp.async.commit_group;" ::: "memory");
            asm volatile("cp.async.wait_group 1;" ::: "memory");
        } else {
            asm volatile("cp.async.wait_group 0;" ::: "memory");
        }
        __syncthreads();

        const int ch0 = chunk_of(r0), s0 = r0 - 9 * ch0;
        const int ch1 = chunk_of(r1), s1 = r1 - 9 * ch1;
        const int pb  = (pr % 3) * SBP_BYTES;

        compute_round(smem, ch0, (s0 / 3) * PW + (s0 % 3), pb,        wm, wn, lane, acc);
        compute_round(smem, ch1, (s1 / 3) * PW + (s1 % 3), pb + 8192, wm, wn, lane, acc);
    }

    // ---- epilogue ----
    const long obb = (long)bb * COUT * (HW * HW);
    #pragma unroll
    for (int nt = 0; nt < 8; nt++) {
        const int n = nb * 128 + wn * 64 + nt * 8 + (lane & 3) * 2;
        const float bv0 = __ldg(bias + n);
        const float bv1 = __ldg(bias + n + 1);
        const long onb = obb + (long)n * (HW * HW);
        #pragma unroll
        for (int mt = 0; mt < 2; mt++) {
            const int m = q0 + wm * 32 + mt * 16 + (lane >> 2);
            {
                const int h = m / PW, w = m % PW;
                if (h < HW && w < HW) {
                    const long o = onb + h * HW + w;
                    out[o]           = acc[mt][nt][0] + bv0;
                    out[o + HW * HW] = acc[mt][nt][1] + bv1;
                }
            }
            {
                const int m2 = m + 8;
                const int h = m2 / PW, w = m2 % PW;
                if (h < HW && w < HW) {
                    const long o = onb + h * HW + w;
                    out[o]           = acc[mt][nt][2] + bv0;
                    out[o + HW * HW] = acc[mt][nt][3] + bv1;
                }
            }
        }
    }
}

// ---------------- launch ----------------
extern "C" void kernel_launch(void* const* d_in, const int* in_sizes, int n_in,
                              void* d_out, int out_size) {
    const float* x  = (const float*)d_in[0];
    const float* W  = (const float*)d_in[1];
    const float* bi = (const float*)d_in[2];
    float* out      = (float*)d_out;

    cudaFuncSetAttribute(conv_main, cudaFuncAttributeMaxDynamicSharedMemorySize,
                         SMEM_TOTAL);

    const int prep_total = N_COPY + N_BORD + N_WRF;
    prep_kernel<<<(prep_total + 255) / 256, 256>>>(x, W);
    conv_main<<<dim3(MTILES, 2, BATCH), 256, SMEM_TOTAL>>>(bi, out);
}

// round 10
// speedup vs baseline: 10.0382x; 1.0952x over previous
#include <cuda_runtime.h>
#include <cuda_fp16.h>
#include <cstdint>

// ============================================================
// Conv2d 3x3 s1 p1: x(32,128,56,56)*W(256,128,3,3)+b -> (32,256,56,56)
// Shifted-GEMM conv on mma.sync.m16n8k16.f32.f16.f16.f32.
// R10: quad windows — ONE barrier + ONE cp.async group per FOUR
// shift-rounds (9 windows, was 18 pairs). All staging issued AFTER
// the window barrier: B ring of 2 quad buffers is then provably safe
// (writer (w+1)%2; all warps past the barrier finished window w-1,
// the only reader of that buffer). A double-buffered per 32-cin chunk
// (halo window 248 px, AQ=248), staged at windows 0/3/5.
// CTA = 128 px x 128 couts, 256 thr, 2 CTAs/SM.
// ============================================================

#define HW        56
#define PW        58
#define CSTRIDE   3584          // half2 units per (b,c2) slice
#define CIN       128
#define COUT      256
#define BATCH     32
#define MTILES    26
#define NWIN      9             // 36 shift-rounds as 9 quad windows
#define AQ        248           // A smem q-stride (half2 units)
#define SA_BYTES  (16 * AQ * 4) // 15872 per A buffer
#define ABUFS     (2 * SA_BYTES)
#define SBQ_BYTES 32768         // B quad buffer (4 rounds x 8KB)
#define SMEM_TOTAL (ABUFS + 2 * SBQ_BYTES)   // 97280

__device__ __half2  g_xpadh[BATCH * 64 * CSTRIDE];
__device__ uint32_t g_wrfh[2 * 4 * 9 * 2048];

#define N_COPY (32 * 64 * 56 * 14)
#define N_BORD (32 * 64 * 448)
#define N_WRF  (2 * 4 * 9 * 2048)

// ---------------- fused prep (identical to R8/R9) ----------------
__global__ void prep_kernel(const float* __restrict__ x, const float* __restrict__ W) {
    int id = blockIdx.x * blockDim.x + threadIdx.x;
    if (id < N_COPY) {
        int f4  = id % 14;
        int h   = (id / 14) % 56;
        int bc2 = id / (14 * 56);
        const float* p0 = x + ((long)bc2 * 2) * 3136 + h * 56 + f4 * 4;
        float4 v0 = *(const float4*)p0;
        float4 v1 = *(const float4*)(p0 + 3136);
        __half2* d = g_xpadh + (long)bc2 * CSTRIDE + (h + 1) * PW + 1 + f4 * 4;
        d[0] = __floats2half2_rn(v0.x, v1.x);
        d[1] = __floats2half2_rn(v0.y, v1.y);
        d[2] = __floats2half2_rn(v0.z, v1.z);
        d[3] = __floats2half2_rn(v0.w, v1.w);
    } else if (id < N_COPY + N_BORD) {
        int t = id - N_COPY;
        int i = t % 448;
        long bc2 = t / 448;
        int pos;
        if (i < 58)       pos = i;
        else if (i < 116) pos = 57 * PW + (i - 58);
        else if (i < 228) {
            int j = i - 116;
            pos = (1 + (j >> 1)) * PW + ((j & 1) ? 57 : 0);
        } else            pos = PW * PW + (i - 228);
        g_xpadh[bc2 * CSTRIDE + pos] = __floats2half2_rn(0.f, 0.f);
    } else if (id < N_COPY + N_BORD + N_WRF) {
        int idx3 = id - N_COPY - N_BORD;
        int blk = idx3 >> 11, within = idx3 & 2047;
        int s = blk % 9, t = blk / 9;
        int chunk = t & 3, nb = t >> 2;
        int u4 = within >> 2, j = within & 3;
        int lane = u4 & 31, t2 = u4 >> 5;
        int kt = t2 & 1, p = t2 >> 1;
        int nt = p * 2 + (j >> 1), reg = j & 1;
        int n = nb * 128 + nt * 8 + (lane >> 2);
        int c = chunk * 32 + kt * 16 + (lane & 3) * 2 + reg * 8;
        __half2 hv = __floats2half2_rn(W[(n * CIN + c) * 9 + s],
                                       W[(n * CIN + c + 1) * 9 + s]);
        g_wrfh[idx3] = *(uint32_t*)&hv;
    }
}

// ---------------- helpers ----------------
__device__ __forceinline__ void mma_f16(float* d, const uint32_t* a, const uint32_t* b) {
    asm volatile(
        "mma.sync.aligned.m16n8k16.row.col.f32.f16.f16.f32 "
        "{%0,%1,%2,%3}, {%4,%5,%6,%7}, {%8,%9}, {%0,%1,%2,%3};"
        : "+f"(d[0]), "+f"(d[1]), "+f"(d[2]), "+f"(d[3])
        : "r"(a[0]), "r"(a[1]), "r"(a[2]), "r"(a[3]), "r"(b[0]), "r"(b[1]));
}
__device__ __forceinline__ void cp_async16(uint32_t sdst, const void* gsrc) {
    asm volatile("cp.async.cg.shared.global [%0], [%1], 16;" :: "r"(sdst), "l"(gsrc));
}
__device__ __forceinline__ uint32_t smem_u32(const void* p) {
    uint32_t a;
    asm("{ .reg .u64 t; cvta.to.shared.u64 t, %1; cvt.u32.u64 %0, t; }" : "=r"(a) : "l"(p));
    return a;
}
__device__ __forceinline__ int chunk_of(int r) {
    return (r >= 27) ? 3 : (r >= 18) ? 2 : (r >= 9) ? 1 : 0;
}

// one shift-round of MMA work
__device__ __forceinline__ void compute_round(
    const char* smem, int chunk, int off, int bofs,
    int wm, int wn, int lane, float acc[2][8][4])
{
    const uint32_t* sA = (const uint32_t*)(smem + (chunk & 1) * SA_BYTES);
    const uint4* sB4 = (const uint4*)(smem + ABUFS + bofs);
    const int qb = off + wm * 32 + (lane >> 2);
    #pragma unroll
    for (int kt = 0; kt < 2; kt++) {
        const uint32_t* arow = sA + (kt * 8 + (lane & 3)) * AQ;
        uint32_t afr[2][4];
        #pragma unroll
        for (int mt = 0; mt < 2; mt++) {
            const int q = qb + mt * 16;
            afr[mt][0] = arow[q];
            afr[mt][1] = arow[q + 8];
            afr[mt][2] = arow[4 * AQ + q];
            afr[mt][3] = arow[4 * AQ + q + 8];
        }
        uint4 bfr[4];
        #pragma unroll
        for (int c4 = 0; c4 < 4; c4++)
            bfr[c4] = sB4[((wn * 4 + c4) * 2 + kt) * 32 + lane];
        #pragma unroll
        for (int mt = 0; mt < 2; mt++)
            #pragma unroll
            for (int c4 = 0; c4 < 4; c4++) {
                mma_f16(acc[mt][c4 * 2],     afr[mt], (const uint32_t*)&bfr[c4]);
                mma_f16(acc[mt][c4 * 2 + 1], afr[mt], ((const uint32_t*)&bfr[c4]) + 2);
            }
    }
}

// ---------------- main ----------------
__global__ void __launch_bounds__(256, 2)
conv_main(const float* __restrict__ bias, float* __restrict__ out) {
    extern __shared__ char smem[];
    const uint32_t smem_b = smem_u32(smem);
    const int tid  = threadIdx.x;
    const int lane = tid & 31;
    const int wid  = tid >> 5;
    const int wm   = wid & 3;          // 4 m-warps: 32 px each
    const int wn   = wid >> 2;         // 2 n-warps: 64 couts each
    const int bb   = blockIdx.z;
    const int nb   = blockIdx.y;       // 0/1
    const int q0   = blockIdx.x * 128;

    const __half2* xpbh = g_xpadh + (long)bb * 64 * CSTRIDE;

    float acc[2][8][4];
    #pragma unroll
    for (int i = 0; i < 2; i++)
        #pragma unroll
        for (int j = 0; j < 8; j++)
            #pragma unroll
            for (int k = 0; k < 4; k++) acc[i][j][k] = 0.0f;

    // A stage: 16 c2-rows x 62 x 16B into buffer sel
    #define STAGE_A(chunk, sel)                                                    \
        do {                                                                       \
            const __half2* asrc = xpbh + (long)((chunk) * 16) * CSTRIDE + q0;      \
            _Pragma("unroll")                                                      \
            for (int it = 0; it < 4; it++) {                                       \
                int aid = it * 256 + tid;                                          \
                if (aid < 16 * 62) {                                               \
                    int row = aid / 62, col = aid - row * 62;                      \
                    cp_async16(smem_b + (sel) * SA_BYTES + (row * AQ + col * 4) * 4, \
                               asrc + (long)row * CSTRIDE + col * 4);              \
                }                                                                  \
            }                                                                      \
        } while (0)

    // stage B for one shift-round r into quad buffer ((r>>2)&1), slot (r&3)
    #define STAGE_B1(r)                                                            \
        do {                                                                       \
            const int ch = chunk_of(r), sh = (r) - 9 * ch;                         \
            const uint32_t* src = g_wrfh                                           \
                + ((size_t)((nb * 4 + ch) * 9 + sh)) * 2048 + tid * 4;             \
            uint32_t dst = smem_b + ABUFS + (((r) >> 2) & 1) * SBQ_BYTES           \
                           + ((r) & 3) * 8192 + tid * 16;                          \
            cp_async16(dst, src);                                                  \
            cp_async16(dst + 4096, src + 1024);                                    \
        } while (0)

    // prologue: window 0 data (B rounds 0..3, A chunk 0 -> buf 0)
    STAGE_B1(0); STAGE_B1(1); STAGE_B1(2); STAGE_B1(3);
    STAGE_A(0, 0);
    asm volatile("cp.async.commit_group;" ::: "memory");

    for (int w = 0; w < NWIN; w++) {
        // wait for this window's data (committed one window ago)
        asm volatile("cp.async.wait_group 0;" ::: "memory");
        __syncthreads();

        // stage next window AFTER the barrier: ring-2 is safe because every
        // warp past this barrier has finished window w-1, the only reader of
        // target buffer (w+1)%2. A targets: buf1 last read r17 (win 4) ->
        // staged at win 5; buf0 last read r8 (win 2) -> staged at win 3.
        if (w + 1 < NWIN) {
            const int r0 = 4 * (w + 1);
            STAGE_B1(r0); STAGE_B1(r0 + 1); STAGE_B1(r0 + 2); STAGE_B1(r0 + 3);
            if (w == 0)      STAGE_A(1, 1);
            else if (w == 3) STAGE_A(2, 0);
            else if (w == 5) STAGE_A(3, 1);
            asm volatile("cp.async.commit_group;" ::: "memory");
        }

        // compute rounds 4w .. 4w+3
        const int qbase = (w & 1) * SBQ_BYTES;
        #pragma unroll
        for (int j = 0; j < 4; j++) {
            const int r  = 4 * w + j;
            const int ch = chunk_of(r);
            const int s  = r - 9 * ch;
            compute_round(smem, ch, (s / 3) * PW + (s % 3), qbase + j * 8192,
                          wm, wn, lane, acc);
        }
    }

    // ---- epilogue ----
    const long obb = (long)bb * COUT * (HW * HW);
    #pragma unroll
    for (int nt = 0; nt < 8; nt++) {
        const int n = nb * 128 + wn * 64 + nt * 8 + (lane & 3) * 2;
        const float bv0 = __ldg(bias + n);
        const float bv1 = __ldg(bias + n + 1);
        const long onb = obb + (long)n * (HW * HW);
        #pragma unroll
        for (int mt = 0; mt < 2; mt++) {
            const int m = q0 + wm * 32 + mt * 16 + (lane >> 2);
            {
                const int h = m / PW, w = m % PW;
                if (h < HW && w < HW) {
                    const long o = onb + h * HW + w;
                    out[o]           = acc[mt][nt][0] + bv0;
                    out[o + HW * HW] = acc[mt][nt][1] + bv1;
                }
            }
            {
                const int m2 = m + 8;
                const int h = m2 / PW, w = m2 % PW;
                if (h < HW && w < HW) {
                    const long o = onb + h * HW + w;
                    out[o]           = acc[mt][nt][2] + bv0;
                    out[o + HW * HW] = acc[mt][nt][3] + bv1;
                }
            }
        }
    }
}

// ---------------- launch ----------------
extern "C" void kernel_launch(void* const* d_in, const int* in_sizes, int n_in,
                              void* d_out, int out_size) {
    const float* x  = (const float*)d_in[0];
    const float* W  = (const float*)d_in[1];
    const float* bi = (const float*)d_in[2];
    float* out      = (float*)d_out;

    cudaFuncSetAttribute(conv_main, cudaFuncAttributeMaxDynamicSharedMemorySize,
                         SMEM_TOTAL);

    const int prep_total = N_COPY + N_BORD + N_WRF;
    prep_kernel<<<(prep_total + 255) / 256, 256>>>(x, W);
    conv_main<<<dim3(MTILES, 2, BATCH), 256, SMEM_TOTAL>>>(bi, out);
}